// round 16
// baseline (speedup 1.0000x reference)
#include <cuda_runtime.h>
#include <cuda_bf16.h>
#include <math.h>
#include <stdint.h>

#define A_N   16
#define H     128
#define IN_D  128
#define NA    32
#define NACT  14
#define TAUF  0.5f
#define BZ    16384
#define T_N   15
#define G3    384   // 3*H

static __device__ float g_scratch[125026304];

__device__ __forceinline__ float sigf(float x){ return 1.0f/(1.0f+__expf(-x)); }

// ============================================================
// warp-level bf16 MMA m16n8k16 (baseline PTX, works on sm_103)
// ============================================================
__device__ __forceinline__ void hmma(float* d, const uint32_t* a, uint32_t b0, uint32_t b1){
    asm volatile("mma.sync.aligned.m16n8k16.row.col.f32.bf16.bf16.f32 "
        "{%0,%1,%2,%3}, {%4,%5,%6,%7}, {%8,%9}, {%0,%1,%2,%3};"
        : "+f"(d[0]), "+f"(d[1]), "+f"(d[2]), "+f"(d[3])
        : "r"(a[0]), "r"(a[1]), "r"(a[2]), "r"(a[3]), "r"(b0), "r"(b1));
}
__device__ __forceinline__ uint32_t packbf(float x, float y){
    __nv_bfloat162 t = __floats2bfloat162_rn(x, y);   // low = x, high = y
    return *reinterpret_cast<uint32_t*>(&t);
}
__device__ __forceinline__ void packsplit(float x, float y, uint32_t& hi, uint32_t& lo){
    uint32_t h = packbf(x, y);
    __nv_bfloat162 bh = *reinterpret_cast<__nv_bfloat162*>(&h);
    hi = h;
    lo = packbf(x - __bfloat162float(bh.x), y - __bfloat162float(bh.y));
}
__device__ __forceinline__ float2 unsplit2(uint32_t hi, uint32_t lo){
    __nv_bfloat162 bh = *reinterpret_cast<__nv_bfloat162*>(&hi);
    __nv_bfloat162 bl = *reinterpret_cast<__nv_bfloat162*>(&lo);
    return make_float2(__bfloat162float(bh.x) + __bfloat162float(bl.x),
                       __bfloat162float(bh.y) + __bfloat162float(bl.y));
}

#define HSMEM 65536   // 2 * 8192 words * 4B (hi + lo W tile)

// ============================================================
// HMMA GEMM: C[m,n] = sum_k A[m*lda+k] * W[n*ldw+wofs+k] (+bias)(+relu)
// K=128 fixed.  CTA = 128 rows x 128-col block; warp = 16 rows.
// 3-term bf16 split, fp32 accumulate.  EPI: 0 none, 1 bias, 2 bias+relu.
// ============================================================
template<int EPI>
__global__ __launch_bounds__(256)
void hgemm(const float* __restrict__ A, int lda,
           const float* __restrict__ W, int ldw, int wofs,
           const float* __restrict__ bias,
           float* __restrict__ C, int ldc, int N)
{
    extern __shared__ uint32_t smw[];     // [hi: 8192][lo: 8192]
    const int tid = threadIdx.x;
    const int w = tid >> 5, lane = tid & 31;
    const int qr = lane >> 2, qc = lane & 3;
    const int colBase = blockIdx.x * 128;
    const int r0 = blockIdx.y * 128 + w * 16 + qr;
    const int r1 = r0 + 8;

    for (int idx = tid; idx < 128 * 64; idx += 256) {
        int n = idx >> 6, ww = idx & 63;
        int gn = colBase + n;
        float2 v = make_float2(0.f, 0.f);
        if (gn < N)
            v = *reinterpret_cast<const float2*>(W + (size_t)gn * ldw + wofs + 2 * ww);
        uint32_t hi, lo; packsplit(v.x, v.y, hi, lo);
        int ws = ww ^ (4 * (n & 7));
        smw[n * 64 + ws]        = hi;
        smw[8192 + n * 64 + ws] = lo;
    }

    float av[16][4];
#pragma unroll
    for (int T = 0; T < 16; T++) {
        float2 p0 = *reinterpret_cast<const float2*>(A + (size_t)r0 * lda + T * 8 + 2 * qc);
        float2 p1 = *reinterpret_cast<const float2*>(A + (size_t)r1 * lda + T * 8 + 2 * qc);
        av[T][0] = p0.x; av[T][1] = p0.y; av[T][2] = p1.x; av[T][3] = p1.y;
    }
    uint32_t Ah[32], Al[32];
#pragma unroll
    for (int kc = 0; kc < 8; kc++) {
#pragma unroll
        for (int half = 0; half < 2; half++) {
            const float* hv = av[2 * kc + half];
            packsplit(hv[0], hv[1], Ah[kc * 4 + 2 * half + 0], Al[kc * 4 + 2 * half + 0]);
            packsplit(hv[2], hv[3], Ah[kc * 4 + 2 * half + 1], Al[kc * 4 + 2 * half + 1]);
        }
    }
    __syncthreads();

    float acc[16][4];
#pragma unroll
    for (int tt = 0; tt < 16; tt++)
#pragma unroll
        for (int j = 0; j < 4; j++) acc[tt][j] = 0.0f;

#pragma unroll
    for (int kc = 0; kc < 8; kc++) {
        const uint32_t* ah = Ah + kc * 4;
        const uint32_t* al = Al + kc * 4;
#pragma unroll
        for (int tt = 0; tt < 16; tt++) {
            int n  = tt * 8 + qr;
            int w0 = kc * 8 + qc;
            int sx = 4 * (n & 7);
            uint32_t bh0 = smw[n * 64 + (w0 ^ sx)];
            uint32_t bh1 = smw[n * 64 + ((w0 + 4) ^ sx)];
            uint32_t bl0 = smw[8192 + n * 64 + (w0 ^ sx)];
            uint32_t bl1 = smw[8192 + n * 64 + ((w0 + 4) ^ sx)];
            hmma(acc[tt], ah, bh0, bh1);
            hmma(acc[tt], al, bh0, bh1);
            hmma(acc[tt], ah, bl0, bl1);
        }
    }

#pragma unroll
    for (int tt = 0; tt < 16; tt++) {
        int n0 = colBase + tt * 8 + 2 * qc;
        if (n0 < N) {
            float b0 = 0.f, b1 = 0.f;
            if (EPI >= 1) { b0 = bias[n0]; b1 = bias[n0 + 1]; }
            float v0 = acc[tt][0] + b0, v1 = acc[tt][1] + b1;
            float v2 = acc[tt][2] + b0, v3 = acc[tt][3] + b1;
            if (EPI == 2) {
                v0 = fmaxf(v0, 0.f); v1 = fmaxf(v1, 0.f);
                v2 = fmaxf(v2, 0.f); v3 = fmaxf(v3, 0.f);
            }
            *reinterpret_cast<float2*>(C + (size_t)r0 * ldc + n0) = make_float2(v0, v1);
            *reinterpret_cast<float2*>(C + (size_t)r1 * ldc + n0) = make_float2(v2, v3);
        }
    }
}

// ============================================================
// HMMA packed input-gate GEMM: gall[BZ][1536] = [gsf|gnf|gsb|gnb]
// ============================================================
__global__ __launch_bounds__(256)
void hgemm_ih(const float* __restrict__ A,
              const float* __restrict__ Wih_f, const float* __restrict__ bih_f,
              const float* __restrict__ Wih_b, const float* __restrict__ bih_b,
              float* __restrict__ C)
{
    extern __shared__ uint32_t smw[];
    const int tid = threadIdx.x;
    const int w = tid >> 5, lane = tid & 31;
    const int qr = lane >> 2, qc = lane & 3;
    const int T = blockIdx.x;                // 0..11
    const int colBase = T * 128;
    const int midx = T / 3;
    const float* W = (midx < 2) ? Wih_f : Wih_b;
    const int wofs = (midx & 1) ? 128 : 0;
    const float* bias = (midx == 0) ? bih_f : (midx == 2) ? bih_b : nullptr;
    const int nlBase = colBase - midx * 384;
    const int r0 = blockIdx.y * 128 + w * 16 + qr;
    const int r1 = r0 + 8;

    for (int idx = tid; idx < 128 * 64; idx += 256) {
        int n = idx >> 6, ww = idx & 63;
        float2 v = *reinterpret_cast<const float2*>(
            W + (size_t)(nlBase + n) * 256 + wofs + 2 * ww);
        uint32_t hi, lo; packsplit(v.x, v.y, hi, lo);
        int ws = ww ^ (4 * (n & 7));
        smw[n * 64 + ws]        = hi;
        smw[8192 + n * 64 + ws] = lo;
    }

    float av[16][4];
#pragma unroll
    for (int t2 = 0; t2 < 16; t2++) {
        float2 p0 = *reinterpret_cast<const float2*>(A + (size_t)r0 * 128 + t2 * 8 + 2 * qc);
        float2 p1 = *reinterpret_cast<const float2*>(A + (size_t)r1 * 128 + t2 * 8 + 2 * qc);
        av[t2][0] = p0.x; av[t2][1] = p0.y; av[t2][2] = p1.x; av[t2][3] = p1.y;
    }
    uint32_t Ah[32], Al[32];
#pragma unroll
    for (int kc = 0; kc < 8; kc++) {
#pragma unroll
        for (int half = 0; half < 2; half++) {
            const float* hv = av[2 * kc + half];
            packsplit(hv[0], hv[1], Ah[kc * 4 + 2 * half + 0], Al[kc * 4 + 2 * half + 0]);
            packsplit(hv[2], hv[3], Ah[kc * 4 + 2 * half + 1], Al[kc * 4 + 2 * half + 1]);
        }
    }
    __syncthreads();

    float acc[16][4];
#pragma unroll
    for (int tt = 0; tt < 16; tt++)
#pragma unroll
        for (int j = 0; j < 4; j++) acc[tt][j] = 0.0f;

#pragma unroll
    for (int kc = 0; kc < 8; kc++) {
        const uint32_t* ah = Ah + kc * 4;
        const uint32_t* al = Al + kc * 4;
#pragma unroll
        for (int tt = 0; tt < 16; tt++) {
            int n  = tt * 8 + qr;
            int w0 = kc * 8 + qc;
            int sx = 4 * (n & 7);
            uint32_t bh0 = smw[n * 64 + (w0 ^ sx)];
            uint32_t bh1 = smw[n * 64 + ((w0 + 4) ^ sx)];
            uint32_t bl0 = smw[8192 + n * 64 + (w0 ^ sx)];
            uint32_t bl1 = smw[8192 + n * 64 + ((w0 + 4) ^ sx)];
            hmma(acc[tt], ah, bh0, bh1);
            hmma(acc[tt], al, bh0, bh1);
            hmma(acc[tt], ah, bl0, bl1);
        }
    }

#pragma unroll
    for (int tt = 0; tt < 16; tt++) {
        int nl = tt * 8 + 2 * qc;
        int n0 = colBase + nl;
        float b0 = 0.f, b1 = 0.f;
        if (bias) { b0 = bias[nlBase + nl]; b1 = bias[nlBase + nl + 1]; }
        *reinterpret_cast<float2*>(C + (size_t)r0 * 1536 + n0) =
            make_float2(acc[tt][0] + b0, acc[tt][1] + b1);
        *reinterpret_cast<float2*>(C + (size_t)r1 * 1536 + n0) =
            make_float2(acc[tt][2] + b0, acc[tt][3] + b1);
    }
}

// ============================================================
// Fused gh GEMM + central GRU: full-width N=384 HMMA (chunked acc),
// epilogue combines with gi and writes hrnn + out_h.
// hprev reconstructed from the Ah/Al bf16 split (error ~2^-17).
// ============================================================
#define BLW 24576            // 384*64 words per buffer
#define GRU_DYN (2 * BLW * 4)

__global__ __launch_bounds__(256, 1)
void hgemm_gru(const float* __restrict__ hidden,
               const float* __restrict__ Whh, const float* __restrict__ bhh,
               const float* __restrict__ gi,
               float* __restrict__ hrnn, float* __restrict__ out_h)
{
    extern __shared__ uint32_t smw[];        // [hi: BLW][lo: BLW]
    __shared__ float sbhh[384];
    const int tid = threadIdx.x;
    const int w = tid >> 5, lane = tid & 31;
    const int qr = lane >> 2, qc = lane & 3;
    const int r0 = blockIdx.x * 128 + w * 16 + qr;
    const int r1 = r0 + 8;

    for (int idx = tid; idx < 384 * 64; idx += 256) {
        int n = idx >> 6, ww = idx & 63;
        float2 v = *reinterpret_cast<const float2*>(Whh + (size_t)n * 128 + 2 * ww);
        uint32_t hi, lo; packsplit(v.x, v.y, hi, lo);
        int ws = ww ^ (4 * (n & 7));
        smw[n * 64 + ws]       = hi;
        smw[BLW + n * 64 + ws] = lo;
    }
    for (int q = tid; q < 384; q += 256) sbhh[q] = bhh[q];

    uint32_t Ah[32], Al[32];
#pragma unroll
    for (int T = 0; T < 16; T++) {
        float2 p0 = *reinterpret_cast<const float2*>(hidden + (size_t)r0 * 128 + T * 8 + 2 * qc);
        float2 p1 = *reinterpret_cast<const float2*>(hidden + (size_t)r1 * 128 + T * 8 + 2 * qc);
        int base = (T >> 1) * 4 + 2 * (T & 1);
        packsplit(p0.x, p0.y, Ah[base],     Al[base]);
        packsplit(p1.x, p1.y, Ah[base + 1], Al[base + 1]);
    }
    __syncthreads();

    const float* gi0 = gi + (size_t)r0 * G3;
    const float* gi1 = gi + (size_t)r1 * G3;

#pragma unroll
    for (int c = 0; c < 4; c++) {
        float acc[3][4][4];
#pragma unroll
        for (int g3 = 0; g3 < 3; g3++)
#pragma unroll
            for (int tt = 0; tt < 4; tt++)
#pragma unroll
                for (int j = 0; j < 4; j++) acc[g3][tt][j] = 0.0f;

#pragma unroll
        for (int kc = 0; kc < 8; kc++) {
            const uint32_t* ah = Ah + kc * 4;
            const uint32_t* al = Al + kc * 4;
#pragma unroll
            for (int g3 = 0; g3 < 3; g3++) {
#pragma unroll
                for (int tt = 0; tt < 4; tt++) {
                    int n  = g3 * 128 + c * 32 + tt * 8 + qr;
                    int w0 = kc * 8 + qc;
                    int sx = 4 * (n & 7);
                    uint32_t bh0 = smw[n * 64 + (w0 ^ sx)];
                    uint32_t bh1 = smw[n * 64 + ((w0 + 4) ^ sx)];
                    uint32_t bl0 = smw[BLW + n * 64 + (w0 ^ sx)];
                    uint32_t bl1 = smw[BLW + n * 64 + ((w0 + 4) ^ sx)];
                    hmma(acc[g3][tt], ah, bh0, bh1);
                    hmma(acc[g3][tt], al, bh0, bh1);
                    hmma(acc[g3][tt], ah, bl0, bl1);
                }
            }
        }

#pragma unroll
        for (int tt = 0; tt < 4; tt++) {
            int T  = c * 4 + tt;
            int co = T * 8 + 2 * qc;
            int ab = (T >> 1) * 4 + 2 * (T & 1);
            float2 hp0 = unsplit2(Ah[ab],     Al[ab]);
            float2 hp1 = unsplit2(Ah[ab + 1], Al[ab + 1]);
            float2 gr0 = *reinterpret_cast<const float2*>(gi0 + co);
            float2 gz0 = *reinterpret_cast<const float2*>(gi0 + 128 + co);
            float2 gn0 = *reinterpret_cast<const float2*>(gi0 + 256 + co);
            float2 gr1 = *reinterpret_cast<const float2*>(gi1 + co);
            float2 gz1 = *reinterpret_cast<const float2*>(gi1 + 128 + co);
            float2 gn1 = *reinterpret_cast<const float2*>(gi1 + 256 + co);

            float gir[4] = { gr0.x, gr0.y, gr1.x, gr1.y };
            float giz[4] = { gz0.x, gz0.y, gz1.x, gz1.y };
            float gin[4] = { gn0.x, gn0.y, gn1.x, gn1.y };
            float hp[4]  = { hp0.x, hp0.y, hp1.x, hp1.y };

            float hv[4];
#pragma unroll
            for (int j = 0; j < 4; j++) {
                int col = co + (j & 1);
                float rr = sigf(gir[j] + acc[0][tt][j] + sbhh[col]);
                float zz = sigf(giz[j] + acc[1][tt][j] + sbhh[128 + col]);
                float nn = tanhf(gin[j] + rr * (acc[2][tt][j] + sbhh[256 + col]));
                hv[j] = (1.0f - zz) * nn + zz * hp[j];
            }
            *reinterpret_cast<float2*>(hrnn  + (size_t)r0 * H + co) = make_float2(hv[0], hv[1]);
            *reinterpret_cast<float2*>(hrnn  + (size_t)r1 * H + co) = make_float2(hv[2], hv[3]);
            *reinterpret_cast<float2*>(out_h + (size_t)r0 * H + co) = make_float2(hv[0], hv[1]);
            *reinterpret_cast<float2*>(out_h + (size_t)r1 * H + co) = make_float2(hv[2], hv[3]);
        }
    }
}

// ============================================================
// HMMA persistent bi-GRU recurrence — 512 threads, 256 rows/CTA.
// grid (BZ/256, 2) = 128 CTAs -> single wave, 16 warps/SM.
// Warps independent after the initial load barrier.
// ============================================================
#define RECUR_DYN (2 * BLW * 4)

__global__ __launch_bounds__(512, 1)
void recur_mma(const float* __restrict__ gall,
               const float* __restrict__ Whh_f, const float* __restrict__ bhh_f,
               const float* __restrict__ Whh_b, const float* __restrict__ bhh_b,
               const float* __restrict__ Wc,
               float2* __restrict__ lpf, float2* __restrict__ lpb)
{
    extern __shared__ uint32_t smw[];        // [hi: BLW][lo: BLW]
    __shared__ float sbhh[384];
    __shared__ float swc[256];

    const int tid  = threadIdx.x;
    const int w    = tid >> 5, lane = tid & 31;
    const int qr   = lane >> 2;
    const int qc   = lane & 3;
    const int dir  = blockIdx.y;
    const int tb   = blockIdx.x * 256;
    const int r0   = tb + w * 16 + qr;
    const int r1   = r0 + 8;
    const int bb   = r0 >> 4;
    const int i0   = qr, i1 = qr + 8;
    const int gofs = dir ? 768 : 0;

    const float* Whh = dir ? Whh_b : Whh_f;
    const float* bhh = dir ? bhh_b : bhh_f;
    float2* lp = dir ? lpb : lpf;

    for (int idx = tid; idx < 384 * 64; idx += 512) {
        int n = idx >> 6, ww = idx & 63;
        float2 v = *reinterpret_cast<const float2*>(Whh + (size_t)n * 128 + 2 * ww);
        uint32_t hi, lo; packsplit(v.x, v.y, hi, lo);
        int ws = ww ^ (4 * (n & 7));
        smw[n * 64 + ws]       = hi;
        smw[BLW + n * 64 + ws] = lo;
    }
    for (int q = tid; q < 384; q += 512) sbhh[q] = bhh[q];
    if (tid < 128) {
        swc[tid]       = Wc[dir * 128 + tid];
        swc[128 + tid] = Wc[256 + dir * 128 + tid];
    }
    __syncthreads();

    float hprev[16][4];
#pragma unroll
    for (int T = 0; T < 16; T++)
#pragma unroll
        for (int j = 0; j < 4; j++) hprev[T][j] = 0.0f;

    const float* gs0 = gall + (size_t)r0 * 1536 + gofs;
    const float* gs1 = gall + (size_t)r1 * 1536 + gofs;

    for (int s = 0; s < T_N; s++) {
        const int t = dir ? (T_N - 1 - s) : s;
        const int j0 = t + (t >= i0);
        const int j1 = t + (t >= i1);
        const float* gn0 = gall + (size_t)((bb << 4) | j0) * 1536 + gofs + 384;
        const float* gn1 = gall + (size_t)((bb << 4) | j1) * 1536 + gofs + 384;

        uint32_t Ah[32], Al[32];
#pragma unroll
        for (int kc = 0; kc < 8; kc++) {
#pragma unroll
            for (int half = 0; half < 2; half++) {
                const float* hv = hprev[2 * kc + half];
                packsplit(hv[0], hv[1], Ah[kc * 4 + 2 * half + 0], Al[kc * 4 + 2 * half + 0]);
                packsplit(hv[2], hv[3], Ah[kc * 4 + 2 * half + 1], Al[kc * 4 + 2 * half + 1]);
            }
        }

        float p0r0 = 0.f, p1r0 = 0.f, p0r1 = 0.f, p1r1 = 0.f;

#pragma unroll
        for (int c = 0; c < 4; c++) {
            float acc[3][4][4];
#pragma unroll
            for (int g3 = 0; g3 < 3; g3++)
#pragma unroll
                for (int tt = 0; tt < 4; tt++)
#pragma unroll
                    for (int j = 0; j < 4; j++) acc[g3][tt][j] = 0.0f;

#pragma unroll
            for (int kc = 0; kc < 8; kc++) {
                const uint32_t* ah = Ah + kc * 4;
                const uint32_t* al = Al + kc * 4;
#pragma unroll
                for (int g3 = 0; g3 < 3; g3++) {
#pragma unroll
                    for (int tt = 0; tt < 4; tt++) {
                        int n   = g3 * 128 + c * 32 + tt * 8 + qr;
                        int w0  = kc * 8 + qc;
                        int sx  = 4 * (n & 7);
                        uint32_t bh0 = smw[n * 64 + (w0 ^ sx)];
                        uint32_t bh1 = smw[n * 64 + ((w0 + 4) ^ sx)];
                        uint32_t bl0 = smw[BLW + n * 64 + (w0 ^ sx)];
                        uint32_t bl1 = smw[BLW + n * 64 + ((w0 + 4) ^ sx)];
                        hmma(acc[g3][tt], ah, bh0, bh1);
                        hmma(acc[g3][tt], al, bh0, bh1);
                        hmma(acc[g3][tt], ah, bl0, bl1);
                    }
                }
            }

#pragma unroll
            for (int tt = 0; tt < 4; tt++) {
                int T  = c * 4 + tt;
                int co = T * 8 + 2 * qc;
                float2 sr0 = *reinterpret_cast<const float2*>(gs0 + co);
                float2 nr0 = *reinterpret_cast<const float2*>(gn0 + co);
                float2 sr1 = *reinterpret_cast<const float2*>(gs1 + co);
                float2 nr1 = *reinterpret_cast<const float2*>(gn1 + co);
                float2 sz0 = *reinterpret_cast<const float2*>(gs0 + 128 + co);
                float2 nz0 = *reinterpret_cast<const float2*>(gn0 + 128 + co);
                float2 sz1 = *reinterpret_cast<const float2*>(gs1 + 128 + co);
                float2 nz1 = *reinterpret_cast<const float2*>(gn1 + 128 + co);
                float2 sn0 = *reinterpret_cast<const float2*>(gs0 + 256 + co);
                float2 nn0 = *reinterpret_cast<const float2*>(gn0 + 256 + co);
                float2 sn1 = *reinterpret_cast<const float2*>(gs1 + 256 + co);
                float2 nn1 = *reinterpret_cast<const float2*>(gn1 + 256 + co);

                float gir[4] = { sr0.x+nr0.x, sr0.y+nr0.y, sr1.x+nr1.x, sr1.y+nr1.y };
                float giz[4] = { sz0.x+nz0.x, sz0.y+nz0.y, sz1.x+nz1.x, sz1.y+nz1.y };
                float gin[4] = { sn0.x+nn0.x, sn0.y+nn0.y, sn1.x+nn1.x, sn1.y+nn1.y };

                float hv[4];
#pragma unroll
                for (int j = 0; j < 4; j++) {
                    int col = co + (j & 1);
                    float rr = sigf(gir[j] + acc[0][tt][j] + sbhh[col]);
                    float zz = sigf(giz[j] + acc[1][tt][j] + sbhh[128 + col]);
                    float nn = tanhf(gin[j] + rr * (acc[2][tt][j] + sbhh[256 + col]));
                    float h  = (1.0f - zz) * nn + zz * hprev[T][j];
                    hprev[T][j] = h;
                    hv[j] = h;
                }
                p0r0 = fmaf(hv[0], swc[co], fmaf(hv[1], swc[co + 1], p0r0));
                p1r0 = fmaf(hv[0], swc[128 + co], fmaf(hv[1], swc[128 + co + 1], p1r0));
                p0r1 = fmaf(hv[2], swc[co], fmaf(hv[3], swc[co + 1], p0r1));
                p1r1 = fmaf(hv[2], swc[128 + co], fmaf(hv[3], swc[128 + co + 1], p1r1));
            }
        }

#pragma unroll
        for (int o = 1; o <= 2; o <<= 1) {
            p0r0 += __shfl_xor_sync(0xFFFFFFFFu, p0r0, o);
            p1r0 += __shfl_xor_sync(0xFFFFFFFFu, p1r0, o);
            p0r1 += __shfl_xor_sync(0xFFFFFFFFu, p0r1, o);
            p1r1 += __shfl_xor_sync(0xFFFFFFFFu, p1r1, o);
        }
        if (qc == 0) {
            lp[(size_t)r0 * T_N + t] = make_float2(p0r0, p1r0);
            lp[(size_t)r1 * T_N + t] = make_float2(p0r1, p1r1);
        }
    }
}

// ============================================================
// hard_w from partial logits + gumbel noise
// ============================================================
__global__ void hard_kernel(const float2* __restrict__ lpf, const float2* __restrict__ lpb,
                            const float* __restrict__ bc, const float* __restrict__ gu,
                            float* __restrict__ hard)
{
    int p = blockIdx.x * 256 + threadIdx.x;
    if (p >= BZ * T_N) return;
    float2 f = lpf[p], b = lpb[p];
    float l0 = f.x + b.x + bc[0];
    float l1 = f.y + b.y + bc[1];
    float u0 = gu[2 * (size_t)p], u1 = gu[2 * (size_t)p + 1];
    float g0 = -logf(-logf(u0 + 1e-10f) + 1e-10f);
    float g1 = -logf(-logf(u1 + 1e-10f) + 1e-10f);
    hard[p] = sigf(((l1 + g1) - (l0 + g0)) / TAUF);
}

// ============================================================
// attention scores + softmax + aggregation.  One warp per (b, i) row.
// ============================================================
__global__ void attn_agg(const float* __restrict__ q, const float* __restrict__ k,
                         const float* __restrict__ hard, const float* __restrict__ hrnn,
                         float* __restrict__ agg)
{
    int warp = threadIdx.x >> 5, lane = threadIdx.x & 31;
    int row = blockIdx.x * 8 + warp;
    int b = row >> 4, i = row & 15;

    float sc = -1e30f, hw = 0.f;
    if (lane < 15) {
        int j = lane + (lane >= i);
        int nrow = (b << 4) | j;
        hw = hard[(size_t)row * 15 + lane];
        const float* qr = q + (size_t)row * NA;
        const float* kr = k + (size_t)nrow * NA;
        float dot = 0.f;
#pragma unroll
        for (int d = 0; d < NA; d++) dot += qr[d] * kr[d];
        sc = dot * hw * 0.17677669529663687f;
    }
    float mx = sc;
#pragma unroll
    for (int o = 16; o; o >>= 1) mx = fmaxf(mx, __shfl_xor_sync(0xFFFFFFFFu, mx, o));
    float ev = (lane < 15) ? __expf(sc - mx) : 0.f;
    float se = ev;
#pragma unroll
    for (int o = 16; o; o >>= 1) se += __shfl_xor_sync(0xFFFFFFFFu, se, o);
    float wgt = (lane < 15) ? hw * (ev / se) : 0.f;

#pragma unroll
    for (int c = 0; c < 4; c++) {
        float acc = 0.f;
#pragma unroll
        for (int m = 0; m < 15; m++) {
            float wm = __shfl_sync(0xFFFFFFFFu, wgt, m);
            int jm = m + (m >= i);
            acc += wm * hrnn[(size_t)((b << 4) | jm) * H + c * 32 + lane];
        }
        agg[(size_t)row * H + c * 32 + lane] = acc;
    }
}

// ============================================================
// out = [hrnn | agg] @ W2^T + b2
// ============================================================
__global__ void out_kernel(const float* __restrict__ hrnn, const float* __restrict__ agg,
                           const float* __restrict__ W2, const float* __restrict__ b2,
                           float* __restrict__ out)
{
    __shared__ float w2s[NACT * 256];
    int tid = threadIdx.x;
    for (int x = tid; x < NACT * 256; x += 256) w2s[x] = W2[x];
    __syncthreads();

    int g = blockIdx.x * 256 + tid;
    if (g >= BZ * NACT) return;
    int row = g / NACT, n = g % NACT;
    const float* hr = hrnn + (size_t)row * H;
    const float* ag = agg  + (size_t)row * H;
    float acc = b2[n];
#pragma unroll 4
    for (int kk = 0; kk < 128; kk++) acc += hr[kk] * w2s[n * 256 + kk];
#pragma unroll 4
    for (int kk = 0; kk < 128; kk++) acc += ag[kk] * w2s[n * 256 + 128 + kk];
    out[g] = acc;
}

// ============================================================
extern "C" void kernel_launch(void* const* d_in, const int* in_sizes, int n_in,
                              void* d_out, int out_size)
{
    const float* inputs = (const float*)d_in[0];
    const float* hidden = (const float*)d_in[1];
    const float* gu     = (const float*)d_in[2];
    const float* W1     = (const float*)d_in[3];
    const float* b1     = (const float*)d_in[4];
    const float* Wih_c  = (const float*)d_in[5];
    const float* Whh_c  = (const float*)d_in[6];
    const float* bih_c  = (const float*)d_in[7];
    const float* bhh_c  = (const float*)d_in[8];
    const float* Wih_f  = (const float*)d_in[9];
    const float* Whh_f  = (const float*)d_in[10];
    const float* bih_f  = (const float*)d_in[11];
    const float* bhh_f  = (const float*)d_in[12];
    const float* Wih_b  = (const float*)d_in[13];
    const float* Whh_b  = (const float*)d_in[14];
    const float* bih_b  = (const float*)d_in[15];
    const float* bhh_b  = (const float*)d_in[16];
    const float* Wc     = (const float*)d_in[17];
    const float* bc     = (const float*)d_in[18];
    const float* Wq     = (const float*)d_in[19];
    const float* Wk     = (const float*)d_in[20];
    const float* W2     = (const float*)d_in[21];
    const float* b2     = (const float*)d_in[22];

    float* S = nullptr;
    cudaGetSymbolAddress((void**)&S, g_scratch);

    const size_t U = (size_t)BZ * H;
    const size_t V = (size_t)BZ * G3;
    float* x1   = S;
    float* gi   = x1 + U;
    float* hrnn = gi + V;
    float* gall = hrnn + U;                       // BZ * 1536
    float* lpfb = gall + (size_t)BZ * 1536;
    float2* lpf = (float2*)lpfb;
    float2* lpb = lpf + (size_t)BZ * T_N;
    float* hard = (float*)(lpb + (size_t)BZ * T_N);
    float* qv   = hard + (size_t)BZ * T_N;
    float* kv   = qv + (size_t)BZ * NA;
    float* agg  = kv + (size_t)BZ * NA;

    float* out   = (float*)d_out;
    float* out_h = out + (size_t)BZ * NACT;

    cudaFuncSetAttribute(recur_mma,
                         cudaFuncAttributeMaxDynamicSharedMemorySize, RECUR_DYN);
    cudaFuncSetAttribute(hgemm_gru,
                         cudaFuncAttributeMaxDynamicSharedMemorySize, GRU_DYN);
    cudaFuncSetAttribute(hgemm<0>,
                         cudaFuncAttributeMaxDynamicSharedMemorySize, HSMEM);
    cudaFuncSetAttribute(hgemm<1>,
                         cudaFuncAttributeMaxDynamicSharedMemorySize, HSMEM);
    cudaFuncSetAttribute(hgemm<2>,
                         cudaFuncAttributeMaxDynamicSharedMemorySize, HSMEM);
    cudaFuncSetAttribute(hgemm_ih,
                         cudaFuncAttributeMaxDynamicSharedMemorySize, HSMEM);

    dim3 blk(256);

    // x1 = relu(inputs @ W1^T + b1)
    hgemm<2><<<dim3(1, BZ/128), blk, HSMEM>>>(inputs, IN_D, W1, IN_D, 0, b1, x1, 128, 128);
    // gi = x1 @ Wih_c^T + bih_c
    hgemm<1><<<dim3(3, BZ/128), blk, HSMEM>>>(x1, H, Wih_c, H, 0, bih_c, gi, G3, G3);
    // fused: gh GEMM + central GRU combine -> hrnn, out_h
    hgemm_gru<<<BZ/128, blk, GRU_DYN>>>(hidden, Whh_c, bhh_c, gi, hrnn, out_h);

    // packed input-gate precompute [gsf|gnf|gsb|gnb]
    hgemm_ih<<<dim3(12, BZ/128), blk, HSMEM>>>(hrnn, Wih_f, bih_f, Wih_b, bih_b, gall);

    // HMMA persistent bi-GRU recurrence (512 threads, 256 rows/CTA, 1 wave)
    recur_mma<<<dim3(BZ/256, 2), dim3(512), RECUR_DYN>>>(gall, Whh_f, bhh_f,
                                                         Whh_b, bhh_b, Wc, lpf, lpb);

    // q, k projections
    hgemm<0><<<dim3(1, BZ/128), blk, HSMEM>>>(hrnn, H, Wq, H, 0, nullptr, qv, NA, NA);
    hgemm<0><<<dim3(1, BZ/128), blk, HSMEM>>>(hrnn, H, Wk, H, 0, nullptr, kv, NA, NA);

    // gumbel hard weights
    hard_kernel<<<(BZ * T_N + 255) / 256, blk>>>(lpf, lpb, bc, gu, hard);

    // attention + aggregation
    attn_agg<<<BZ / 8, blk>>>(qv, kv, hard, hrnn, agg);

    // output head
    out_kernel<<<(BZ * NACT + 255) / 256, blk>>>(hrnn, agg, W2, b2, out);
}